// round 6
// baseline (speedup 1.0000x reference)
#include <cuda_runtime.h>
#include <cuda_fp16.h>
#include <math_constants.h>
#include <cstdint>

// Problem constants
#define S2    2048
#define HID   1024
#define NH    16
#define HD    64
#define BATCH 2

// Scratch for projected Q and V in [B, H, S, d] layout (16 MB each).
__device__ float g_q[BATCH * NH * S2 * HD];
__device__ float g_v[BATCH * NH * S2 * HD];

// ---------------------------------------------------------------------------
// FP16 tensor-core projection GEMM: C[m,n] = A[m,:] @ W[:,n] + bias[n]
// fp16 inputs (10-bit mantissa ~= TF32), fp32 accumulate -> same error class
// as the TF32 version but 2x the mma rate.
// Block 128x128, k-block 32, double-buffered smem, ldmatrix operand loads.
// 8 warps, each 64(m) x 32(n) via mma.sync m16n8k16 (4 m-frags x 4 n-frags).
// ---------------------------------------------------------------------------
#define PKB 32
#define AKP 40    // A smem k-pad (halves): 8-row ldmatrix groups conflict-free
#define BNP 136   // B smem n-pad (halves)

__device__ __forceinline__ uint2 f4_to_h4(float4 v) {
    __half2 h0 = __floats2half2_rn(v.x, v.y);
    __half2 h1 = __floats2half2_rn(v.z, v.w);
    uint2 r;
    r.x = *(uint32_t*)&h0;
    r.y = *(uint32_t*)&h1;
    return r;
}

__device__ __forceinline__ void ldsm_x4(uint32_t& r0, uint32_t& r1,
                                        uint32_t& r2, uint32_t& r3,
                                        const __half* p) {
    uint32_t a = (uint32_t)__cvta_generic_to_shared(p);
    asm volatile("ldmatrix.sync.aligned.m8n8.x4.shared.b16 {%0,%1,%2,%3}, [%4];"
                 : "=r"(r0), "=r"(r1), "=r"(r2), "=r"(r3) : "r"(a));
}

__device__ __forceinline__ void ldsm_x2_trans(uint32_t& r0, uint32_t& r1,
                                              const __half* p) {
    uint32_t a = (uint32_t)__cvta_generic_to_shared(p);
    asm volatile("ldmatrix.sync.aligned.m8n8.x2.trans.shared.b16 {%0,%1}, [%2];"
                 : "=r"(r0), "=r"(r1) : "r"(a));
}

__device__ __forceinline__ void mma_f16(float c[4], const uint32_t a[4],
                                        const uint32_t b[2]) {
    asm volatile(
        "mma.sync.aligned.m16n8k16.row.col.f32.f16.f16.f32 "
        "{%0,%1,%2,%3}, {%4,%5,%6,%7}, {%8,%9}, {%0,%1,%2,%3};"
        : "+f"(c[0]), "+f"(c[1]), "+f"(c[2]), "+f"(c[3])
        : "r"(a[0]), "r"(a[1]), "r"(a[2]), "r"(a[3]), "r"(b[0]), "r"(b[1]));
}

__global__ __launch_bounds__(256)
void proj_kernel(const float* __restrict__ A,
                 const float* __restrict__ Wq, const float* __restrict__ bq,
                 const float* __restrict__ Wv, const float* __restrict__ bv)
{
    const float* __restrict__ W    = blockIdx.z ? Wv : Wq;
    const float* __restrict__ bias = blockIdx.z ? bv : bq;
    float* __restrict__ out        = blockIdx.z ? g_v : g_q;

    __shared__ __half As[2][128][AKP];   // [m][k] row-major halves
    __shared__ __half Bs[2][PKB][BNP];   // [k][n] row-major halves

    const int tid  = threadIdx.x;
    const int lane = tid & 31;
    const int wid  = tid >> 5;
    const int gid  = lane >> 2;
    const int tig  = lane & 3;
    const int m0   = blockIdx.y * 128;
    const int n0   = blockIdx.x * 128;

    const int mBase = (wid >> 2) * 64;
    const int nBase = (wid & 3) * 32;

    // ldmatrix per-lane address components
    const int a_row = (lane & 7) + 8 * ((lane >> 3) & 1);
    const int a_col = 8 * (lane >> 4);
    const int b_row = lane & 15;

    float c[4][4][4];
    #pragma unroll
    for (int f = 0; f < 4; f++)
        #pragma unroll
        for (int g = 0; g < 4; g++)
            #pragma unroll
            for (int i = 0; i < 4; i++) c[f][g][i] = 0.0f;

    uint2 pa[4], pb[4];

    // prologue: load k-block 0
    #pragma unroll
    for (int p = 0; p < 4; p++) {
        int s = tid + 256 * p;
        int m = s >> 3, kq = s & 7;
        pa[p] = f4_to_h4(*(const float4*)(A + (size_t)(m0 + m) * HID + 4 * kq));
        int kr = s >> 5, nq = s & 31;
        pb[p] = f4_to_h4(*(const float4*)(W + (size_t)kr * HID + n0 + 4 * nq));
    }
    #pragma unroll
    for (int p = 0; p < 4; p++) {
        int s = tid + 256 * p;
        int m = s >> 3, kq = s & 7;
        *(uint2*)&As[0][m][4 * kq] = pa[p];
        int kr = s >> 5, nq = s & 31;
        *(uint2*)&Bs[0][kr][4 * nq] = pb[p];
    }
    __syncthreads();

    const int NKB = HID / PKB;   // 32
    for (int kb = 0; kb < NKB; kb++) {
        const int cur = kb & 1;
        const int nxt = cur ^ 1;

        if (kb + 1 < NKB) {
            const int kk = (kb + 1) * PKB;
            #pragma unroll
            for (int p = 0; p < 4; p++) {
                int s = tid + 256 * p;
                int m = s >> 3, kq = s & 7;
                pa[p] = f4_to_h4(*(const float4*)(A + (size_t)(m0 + m) * HID + kk + 4 * kq));
                int kr = s >> 5, nq = s & 31;
                pb[p] = f4_to_h4(*(const float4*)(W + (size_t)(kk + kr) * HID + n0 + 4 * nq));
            }
        }

        #pragma unroll
        for (int ks = 0; ks < PKB; ks += 16) {
            uint32_t a[4][4], b[4][2];
            #pragma unroll
            for (int f = 0; f < 4; f++)
                ldsm_x4(a[f][0], a[f][1], a[f][2], a[f][3],
                        &As[cur][mBase + 16 * f + a_row][ks + a_col]);
            #pragma unroll
            for (int g = 0; g < 4; g++)
                ldsm_x2_trans(b[g][0], b[g][1],
                              &Bs[cur][ks + b_row][nBase + 8 * g]);
            #pragma unroll
            for (int f = 0; f < 4; f++)
                #pragma unroll
                for (int g = 0; g < 4; g++)
                    mma_f16(c[f][g], a[f], b[g]);
        }

        if (kb + 1 < NKB) {
            #pragma unroll
            for (int p = 0; p < 4; p++) {
                int s = tid + 256 * p;
                int m = s >> 3, kq = s & 7;
                *(uint2*)&As[nxt][m][4 * kq] = pa[p];
                int kr = s >> 5, nq = s & 31;
                *(uint2*)&Bs[nxt][kr][4 * nq] = pb[p];
            }
        }
        __syncthreads();
    }

    // Epilogue: bias + scatter to [B,H,S,d] (c-frag layout same as m16n8k8).
    #pragma unroll
    for (int g = 0; g < 4; g++) {
        const int n  = n0 + nBase + 8 * g + 2 * tig;
        const int h  = n >> 6;
        const int cc = n & 63;
        const float b0 = bias[n];
        const float b1 = bias[n + 1];
        #pragma unroll
        for (int f = 0; f < 4; f++) {
            #pragma unroll
            for (int half = 0; half < 2; half++) {
                int m  = m0 + mBase + 16 * f + gid + 8 * half;
                int bb = m >> 11;
                int s  = m & 2047;
                float2 o;
                o.x = c[f][g][2 * half + 0] + b0;
                o.y = c[f][g][2 * half + 1] + b1;
                *(float2*)(out + (((size_t)(bb * NH + h) * S2 + s) * HD + cc)) = o;
            }
        }
    }
}

// ---------------------------------------------------------------------------
// Tiled sparse attention, TQ=64 / 192-key window.
// Block: 64 query rows of one (b,h). 8 warps; warp ty owns rows 8ty..8ty+7.
// Thread tile 8q x 6k (score), 8q x 2d (ctx). Strided scores kept in regs
// (lane t-2 holds t's score). Cstr aliases Qs; V aliases K.
// smem: Kt 64x193 / V 192x64 (union) + Qs 64x68 / Cstr 64x64 (union)
//       + Ps 64x192 = 115,968 B -> 2 CTAs/SM.
// Masked entries are exactly 0 after softmax (fp32 exp underflow) -> exact.
// ---------------------------------------------------------------------------
#define TQ   64
#define WIN  192
#define KTP  193
#define QSP  68
#define PSW  192

#define ATTN_SMEM_FLOATS (64*KTP + 64*QSP + TQ*PSW)
#define ATTN_SMEM_BYTES  (ATTN_SMEM_FLOATS * 4)

__global__ __launch_bounds__(256, 2)
void attn_kernel(const float* __restrict__ amask, float* __restrict__ out)
{
    extern __shared__ float sm[];
    float* KVu = sm;                    // Kt [d][193] then V [c][64]
    float* QCu = KVu + 64 * KTP;        // Qs [d][68] then Cstr [r][64]
    float* Ps  = QCu + 64 * QSP;        // [r][192]
    float* Qs   = QCu;
    float* Cstr = QCu;

    const int tid = threadIdx.x;
    const int tx  = tid & 31;
    const int ty  = tid >> 5;
    const int I0  = blockIdx.x * TQ;
    const int bh  = blockIdx.y;
    const int b   = bh >> 4;
    const int jbase = I0 - 128;

    const float* __restrict__ q  = g_q + (size_t)bh * S2 * HD;
    const float* __restrict__ v  = g_v + (size_t)bh * S2 * HD;
    const float* __restrict__ am = amask + b * S2;

    // ---- stage Q (transposed [d][68]) and K window (transposed [d][193]) ----
    for (int idx = tid; idx < TQ * HD; idx += 256) {
        int r = idx >> 6, d = idx & 63;
        Qs[d * QSP + r] = q[(size_t)(I0 + r) * HD + d];
    }
    for (int idx = tid; idx < WIN * HD; idx += 256) {
        int c = idx >> 6, d = idx & 63;
        int j = jbase + c;
        KVu[d * KTP + c] = (j >= 0) ? q[(size_t)j * HD + d] : 0.0f;
    }
    __syncthreads();

    // ---- dense score GEMM: 8 queries x 6 keys per thread ----
    float acc[8][6];
    #pragma unroll
    for (int qi = 0; qi < 8; qi++)
        #pragma unroll
        for (int u = 0; u < 6; u++) acc[qi][u] = 0.0f;

    #pragma unroll 4
    for (int d = 0; d < 64; d++) {
        float4 alo = *(const float4*)&Qs[d * QSP + 8 * ty];
        float4 ahi = *(const float4*)&Qs[d * QSP + 8 * ty + 4];
        float aq[8] = {alo.x, alo.y, alo.z, alo.w, ahi.x, ahi.y, ahi.z, ahi.w};
        #pragma unroll
        for (int u = 0; u < 6; u++) {
            float bb = KVu[d * KTP + tx + 32 * u];
            #pragma unroll
            for (int qi = 0; qi < 8; qi++)
                acc[qi][u] = fmaf(aq[qi], bb, acc[qi][u]);
        }
    }

    // mask + scale + attention_mask -> Ps row-major
    #pragma unroll
    for (int u = 0; u < 6; u++) {
        int c = tx + 32 * u;
        int j = jbase + c;
        float amv = (j >= 0) ? am[j] : 0.0f;
        #pragma unroll
        for (int qi = 0; qi < 8; qi++) {
            int r = 8 * ty + qi;
            bool ok = (c >= r) && (c <= r + 128) && (j >= 0);
            Ps[r * PSW + c] = ok ? (acc[qi][u] * 0.125f + amv) : -CUDART_INF_F;
        }
    }
    __syncthreads();   // K reads done -> safe to overwrite with V

    // ---- stage V window row-major [c][64] (float4) ----
    for (int idx = tid; idx < WIN * 16; idx += 256) {
        int c = idx >> 4, dq = idx & 15;
        int j = jbase + c;
        float4 val = (j >= 0) ? *(const float4*)(v + (size_t)j * HD + 4 * dq)
                              : make_float4(0.f, 0.f, 0.f, 0.f);
        *(float4*)(KVu + c * HD + 4 * dq) = val;
    }

    // ---- strided scores (t >= 2), kept in registers: lane t-2 owns t ----
    float sreg[8];
    #pragma unroll
    for (int qi = 0; qi < 8; qi++) sreg[qi] = -CUDART_INF_F;

    #pragma unroll
    for (int qi = 0; qi < 8; qi++) {
        int r = 8 * ty + qi;
        int i = I0 + r;
        int nstr = i >> 7;
        float qa = Qs[tx * QSP + r];
        float qb = Qs[(tx + 32) * QSP + r];
        for (int t = 2; t <= nstr; t++) {
            int j = i - (t << 7);
            float ka = q[(size_t)j * HD + tx];
            float kb = q[(size_t)j * HD + tx + 32];
            float p = qa * ka + qb * kb;
            p += __shfl_xor_sync(0xffffffffu, p, 16);
            p += __shfl_xor_sync(0xffffffffu, p, 8);
            p += __shfl_xor_sync(0xffffffffu, p, 4);
            p += __shfl_xor_sync(0xffffffffu, p, 2);
            p += __shfl_xor_sync(0xffffffffu, p, 1);
            float pv = p * 0.125f + am[j];
            if (tx == t - 2) sreg[qi] = pv;
        }
    }
    __syncthreads();   // Qs dead -> Cstr may alias it

    // ---- softmax + strided ctx ----
    #pragma unroll
    for (int qi = 0; qi < 8; qi++) {
        int r = 8 * ty + qi;
        int i = I0 + r;
        int nstr = i >> 7;

        float mx = sreg[qi];
        #pragma unroll
        for (int u = 0; u < 6; u++) mx = fmaxf(mx, Ps[r * PSW + tx + 32 * u]);
        mx = fmaxf(mx, __shfl_xor_sync(0xffffffffu, mx, 16));
        mx = fmaxf(mx, __shfl_xor_sync(0xffffffffu, mx, 8));
        mx = fmaxf(mx, __shfl_xor_sync(0xffffffffu, mx, 4));
        mx = fmaxf(mx, __shfl_xor_sync(0xffffffffu, mx, 2));
        mx = fmaxf(mx, __shfl_xor_sync(0xffffffffu, mx, 1));

        float e[6];
        float s = 0.0f;
        #pragma unroll
        for (int u = 0; u < 6; u++) {
            e[u] = __expf(Ps[r * PSW + tx + 32 * u] - mx);
            s += e[u];
        }
        float es = __expf(sreg[qi] - mx);   // -inf lanes -> 0
        s += es;
        s += __shfl_xor_sync(0xffffffffu, s, 16);
        s += __shfl_xor_sync(0xffffffffu, s, 8);
        s += __shfl_xor_sync(0xffffffffu, s, 4);
        s += __shfl_xor_sync(0xffffffffu, s, 2);
        s += __shfl_xor_sync(0xffffffffu, s, 1);
        float inv = 1.0f / s;

        #pragma unroll
        for (int u = 0; u < 6; u++) Ps[r * PSW + tx + 32 * u] = e[u] * inv;

        // strided ctx: lanes over d; p broadcast from lane (t-2)
        float ax = 0.0f, ay = 0.0f;
        float pn = es * inv;
        for (int t = 2; t <= nstr; t++) {
            float p = __shfl_sync(0xffffffffu, pn, t - 2);
            int j = i - (t << 7);
            ax = fmaf(p, v[(size_t)j * HD + tx], ax);
            ay = fmaf(p, v[(size_t)j * HD + tx + 32], ay);
        }
        Cstr[r * 64 + tx]      = ax;
        Cstr[r * 64 + tx + 32] = ay;
    }
    __syncthreads();   // V staged + Ps normalized + Cstr written

    // ---- dense ctx GEMM: 8 queries x 2 d-cols per thread, c in pairs ----
    float o[8][2];
    #pragma unroll
    for (int qi = 0; qi < 8; qi++) { o[qi][0] = 0.0f; o[qi][1] = 0.0f; }

    #pragma unroll 2
    for (int c2 = 0; c2 < WIN / 2; c2++) {
        float2 v0 = *(const float2*)(KVu + (2 * c2 + 0) * HD + 2 * tx);
        float2 v1 = *(const float2*)(KVu + (2 * c2 + 1) * HD + 2 * tx);
        #pragma unroll
        for (int qi = 0; qi < 8; qi++) {
            float2 pp = *(const float2*)&Ps[(8 * ty + qi) * PSW + 2 * c2];
            o[qi][0] = fmaf(pp.x, v0.x, fmaf(pp.y, v1.x, o[qi][0]));
            o[qi][1] = fmaf(pp.x, v0.y, fmaf(pp.y, v1.y, o[qi][1]));
        }
    }

    // ---- epilogue: add strided ctx, store [B, S, H*64] ----
    #pragma unroll
    for (int qi = 0; qi < 8; qi++) {
        int r = 8 * ty + qi;
        int i = I0 + r;
        float2 cs = *(const float2*)(Cstr + r * 64 + 2 * tx);
        float2 res;
        res.x = o[qi][0] + cs.x;
        res.y = o[qi][1] + cs.y;
        *(float2*)(out + ((size_t)(b * S2 + i) * (NH * HD)) + (bh & 15) * HD + 2 * tx) = res;
    }
}

// ---------------------------------------------------------------------------
// Launch
// Inputs (metadata order): hidden_states, attention_mask, W_q, b_q, W_v, b_v
// ---------------------------------------------------------------------------
extern "C" void kernel_launch(void* const* d_in, const int* in_sizes, int n_in,
                              void* d_out, int out_size)
{
    const float* hidden = (const float*)d_in[0];
    const float* amask  = (const float*)d_in[1];
    const float* Wq     = (const float*)d_in[2];
    const float* bq     = (const float*)d_in[3];
    const float* Wv     = (const float*)d_in[4];
    const float* bv     = (const float*)d_in[5];
    float* out = (float*)d_out;

    cudaFuncSetAttribute(attn_kernel,
                         cudaFuncAttributeMaxDynamicSharedMemorySize,
                         ATTN_SMEM_BYTES);

    dim3 pgrid(HID / 128, (BATCH * S2) / 128, 2);   // (8, 32, 2)
    proj_kernel<<<pgrid, 256>>>(hidden, Wq, bq, Wv, bv);

    dim3 agrid(S2 / TQ, BATCH * NH);                // (32, 32)
    attn_kernel<<<agrid, 256, ATTN_SMEM_BYTES>>>(amask, out);
}

// round 7
// speedup vs baseline: 1.5011x; 1.5011x over previous
#include <cuda_runtime.h>
#include <cuda_fp16.h>
#include <math_constants.h>
#include <cstdint>

// Problem constants
#define S2    2048
#define HID   1024
#define NH    16
#define HD    64
#define BATCH 2

// Scratch for projected Q and V in [B, H, S, d] layout (16 MB each).
__device__ float g_q[BATCH * NH * S2 * HD];
__device__ float g_v[BATCH * NH * S2 * HD];

// ---------------------------------------------------------------------------
// FP16 tensor-core projection GEMM (measured ~47us for both projections).
// fp16 inputs (10-bit mantissa ~= TF32), fp32 accumulate.
// Block 128x128, k-block 32, double-buffered smem, ldmatrix operand loads.
// 8 warps, each 64(m) x 32(n) via mma.sync m16n8k16 (4 m-frags x 4 n-frags).
// ---------------------------------------------------------------------------
#define PKB 32
#define AKP 40    // A smem k-pad (halves)
#define BNP 136   // B smem n-pad (halves)

__device__ __forceinline__ uint2 f4_to_h4(float4 v) {
    __half2 h0 = __floats2half2_rn(v.x, v.y);
    __half2 h1 = __floats2half2_rn(v.z, v.w);
    uint2 r;
    r.x = *(uint32_t*)&h0;
    r.y = *(uint32_t*)&h1;
    return r;
}

__device__ __forceinline__ void ldsm_x4(uint32_t& r0, uint32_t& r1,
                                        uint32_t& r2, uint32_t& r3,
                                        const __half* p) {
    uint32_t a = (uint32_t)__cvta_generic_to_shared(p);
    asm volatile("ldmatrix.sync.aligned.m8n8.x4.shared.b16 {%0,%1,%2,%3}, [%4];"
                 : "=r"(r0), "=r"(r1), "=r"(r2), "=r"(r3) : "r"(a));
}

__device__ __forceinline__ void ldsm_x2_trans(uint32_t& r0, uint32_t& r1,
                                              const __half* p) {
    uint32_t a = (uint32_t)__cvta_generic_to_shared(p);
    asm volatile("ldmatrix.sync.aligned.m8n8.x2.trans.shared.b16 {%0,%1}, [%2];"
                 : "=r"(r0), "=r"(r1) : "r"(a));
}

__device__ __forceinline__ void mma_f16(float c[4], const uint32_t a[4],
                                        const uint32_t b[2]) {
    asm volatile(
        "mma.sync.aligned.m16n8k16.row.col.f32.f16.f16.f32 "
        "{%0,%1,%2,%3}, {%4,%5,%6,%7}, {%8,%9}, {%0,%1,%2,%3};"
        : "+f"(c[0]), "+f"(c[1]), "+f"(c[2]), "+f"(c[3])
        : "r"(a[0]), "r"(a[1]), "r"(a[2]), "r"(a[3]), "r"(b[0]), "r"(b[1]));
}

__global__ __launch_bounds__(256)
void proj_kernel(const float* __restrict__ A,
                 const float* __restrict__ Wq, const float* __restrict__ bq,
                 const float* __restrict__ Wv, const float* __restrict__ bv)
{
    const float* __restrict__ W    = blockIdx.z ? Wv : Wq;
    const float* __restrict__ bias = blockIdx.z ? bv : bq;
    float* __restrict__ out        = blockIdx.z ? g_v : g_q;

    __shared__ __half As[2][128][AKP];   // [m][k] row-major halves
    __shared__ __half Bs[2][PKB][BNP];   // [k][n] row-major halves

    const int tid  = threadIdx.x;
    const int lane = tid & 31;
    const int wid  = tid >> 5;
    const int gid  = lane >> 2;
    const int tig  = lane & 3;
    const int m0   = blockIdx.y * 128;
    const int n0   = blockIdx.x * 128;

    const int mBase = (wid >> 2) * 64;
    const int nBase = (wid & 3) * 32;

    const int a_row = (lane & 7) + 8 * ((lane >> 3) & 1);
    const int a_col = 8 * (lane >> 4);
    const int b_row = lane & 15;

    float c[4][4][4];
    #pragma unroll
    for (int f = 0; f < 4; f++)
        #pragma unroll
        for (int g = 0; g < 4; g++)
            #pragma unroll
            for (int i = 0; i < 4; i++) c[f][g][i] = 0.0f;

    uint2 pa[4], pb[4];

    #pragma unroll
    for (int p = 0; p < 4; p++) {
        int s = tid + 256 * p;
        int m = s >> 3, kq = s & 7;
        pa[p] = f4_to_h4(*(const float4*)(A + (size_t)(m0 + m) * HID + 4 * kq));
        int kr = s >> 5, nq = s & 31;
        pb[p] = f4_to_h4(*(const float4*)(W + (size_t)kr * HID + n0 + 4 * nq));
    }
    #pragma unroll
    for (int p = 0; p < 4; p++) {
        int s = tid + 256 * p;
        int m = s >> 3, kq = s & 7;
        *(uint2*)&As[0][m][4 * kq] = pa[p];
        int kr = s >> 5, nq = s & 31;
        *(uint2*)&Bs[0][kr][4 * nq] = pb[p];
    }
    __syncthreads();

    const int NKB = HID / PKB;   // 32
    for (int kb = 0; kb < NKB; kb++) {
        const int cur = kb & 1;
        const int nxt = cur ^ 1;

        if (kb + 1 < NKB) {
            const int kk = (kb + 1) * PKB;
            #pragma unroll
            for (int p = 0; p < 4; p++) {
                int s = tid + 256 * p;
                int m = s >> 3, kq = s & 7;
                pa[p] = f4_to_h4(*(const float4*)(A + (size_t)(m0 + m) * HID + kk + 4 * kq));
                int kr = s >> 5, nq = s & 31;
                pb[p] = f4_to_h4(*(const float4*)(W + (size_t)(kk + kr) * HID + n0 + 4 * nq));
            }
        }

        #pragma unroll
        for (int ks = 0; ks < PKB; ks += 16) {
            uint32_t a[4][4], b[4][2];
            #pragma unroll
            for (int f = 0; f < 4; f++)
                ldsm_x4(a[f][0], a[f][1], a[f][2], a[f][3],
                        &As[cur][mBase + 16 * f + a_row][ks + a_col]);
            #pragma unroll
            for (int g = 0; g < 4; g++)
                ldsm_x2_trans(b[g][0], b[g][1],
                              &Bs[cur][ks + b_row][nBase + 8 * g]);
            #pragma unroll
            for (int f = 0; f < 4; f++)
                #pragma unroll
                for (int g = 0; g < 4; g++)
                    mma_f16(c[f][g], a[f], b[g]);
        }

        if (kb + 1 < NKB) {
            #pragma unroll
            for (int p = 0; p < 4; p++) {
                int s = tid + 256 * p;
                int m = s >> 3, kq = s & 7;
                *(uint2*)&As[nxt][m][4 * kq] = pa[p];
                int kr = s >> 5, nq = s & 31;
                *(uint2*)&Bs[nxt][kr][4 * nq] = pb[p];
            }
        }
        __syncthreads();
    }

    #pragma unroll
    for (int g = 0; g < 4; g++) {
        const int n  = n0 + nBase + 8 * g + 2 * tig;
        const int h  = n >> 6;
        const int cc = n & 63;
        const float b0 = bias[n];
        const float b1 = bias[n + 1];
        #pragma unroll
        for (int f = 0; f < 4; f++) {
            #pragma unroll
            for (int half = 0; half < 2; half++) {
                int m  = m0 + mBase + 16 * f + gid + 8 * half;
                int bb = m >> 11;
                int s  = m & 2047;
                float2 o;
                o.x = c[f][g][2 * half + 0] + b0;
                o.y = c[f][g][2 * half + 1] + b1;
                *(float2*)(out + (((size_t)(bb * NH + h) * S2 + s) * HD + cc)) = o;
            }
        }
    }
}

// ---------------------------------------------------------------------------
// Tiled sparse attention (round-5 version, measured 165us @ 3 CTAs/SM).
// KV: 64x161 (K transposed, score phase) / 160x64 (V row-major, ctx phase)
// QC: Qs 64x33 (score + strided phases), then ALIASED as Cstr 32x66 after a
//     full __syncthreads separates last Qs read from first Cstr write.
// Ps: 160x33, Sstr: 32x16.  Total 18208 floats = 72832 B -> 3 CTAs/SM.
// Masked entries are exactly 0 after softmax (fp32 exp underflow) -> exact.
// ---------------------------------------------------------------------------
#define TQ    32
#define WIN   160
#define KPAD  161
#define QPAD  33
#define PPAD  33
#define CPAD  66

#define ATTN_SMEM_FLOATS (64*KPAD + 64*QPAD + WIN*PPAD + TQ*16)
#define ATTN_SMEM_BYTES  (ATTN_SMEM_FLOATS * 4)

__global__ __launch_bounds__(256, 3)
void attn_kernel(const float* __restrict__ amask, float* __restrict__ out)
{
    extern __shared__ float sm[];
    float* KV   = sm;                        // 64*161
    float* QC   = KV + 64 * KPAD;            // Qs then Cstr (2112 floats)
    float* Ps   = QC + 64 * QPAD;            // 160*33
    float* Sstr = Ps + WIN * PPAD;           // 32*16
    float* Qs   = QC;
    float* Cstr = QC;

    const int tid = threadIdx.x;
    const int tx  = tid & 31;
    const int ty  = tid >> 5;
    const int I0  = blockIdx.x * TQ;
    const int bh  = blockIdx.y;
    const int b   = bh >> 4;
    const int jbase = I0 - 128;

    const float* __restrict__ q  = g_q + (size_t)bh * S2 * HD;
    const float* __restrict__ v  = g_v + (size_t)bh * S2 * HD;
    const float* __restrict__ am = amask + b * S2;

    // ---- stage Q tile (transposed) and K window (transposed) ----
    for (int idx = tid; idx < TQ * HD; idx += 256) {
        int r = idx >> 6, d = idx & 63;
        Qs[d * QPAD + r] = q[(size_t)(I0 + r) * HD + d];
    }
    for (int idx = tid; idx < WIN * HD; idx += 256) {
        int c = idx >> 6, d = idx & 63;
        int j = jbase + c;
        KV[d * KPAD + c] = (j >= 0) ? q[(size_t)j * HD + d] : 0.0f;
    }
    __syncthreads();

    // ---- dense score GEMM: 4 queries x 5 keys per thread ----
    float acc[4][5];
    #pragma unroll
    for (int qi = 0; qi < 4; qi++)
        #pragma unroll
        for (int u = 0; u < 5; u++) acc[qi][u] = 0.0f;

    #pragma unroll 8
    for (int d = 0; d < 64; d++) {
        float a0 = Qs[d * QPAD + ty * 4 + 0];
        float a1 = Qs[d * QPAD + ty * 4 + 1];
        float a2 = Qs[d * QPAD + ty * 4 + 2];
        float a3 = Qs[d * QPAD + ty * 4 + 3];
        #pragma unroll
        for (int u = 0; u < 5; u++) {
            float bb = KV[d * KPAD + tx + 32 * u];
            acc[0][u] = fmaf(a0, bb, acc[0][u]);
            acc[1][u] = fmaf(a1, bb, acc[1][u]);
            acc[2][u] = fmaf(a2, bb, acc[2][u]);
            acc[3][u] = fmaf(a3, bb, acc[3][u]);
        }
    }

    // mask + scale + attention_mask; transposed P buffer
    #pragma unroll
    for (int u = 0; u < 5; u++) {
        int c = tx + 32 * u;
        int j = jbase + c;
        float amv = (j >= 0) ? am[j] : 0.0f;
        #pragma unroll
        for (int qi = 0; qi < 4; qi++) {
            int r = ty * 4 + qi;
            bool ok = (c >= r) && (c <= r + 128) && (j >= 0);
            Ps[c * PPAD + r] = ok ? (acc[qi][u] * 0.125f + amv) : -CUDART_INF_F;
        }
    }
    __syncthreads();   // KV-K reads done -> safe to overwrite with V

    // ---- reload KV buffer with V window (row-major) ----
    for (int idx = tid; idx < WIN * HD; idx += 256) {
        int c = idx >> 6, d = idx & 63;
        int j = jbase + c;
        KV[c * HD + d] = (j >= 0) ? v[(size_t)j * HD + d] : 0.0f;
    }

    // ---- strided scores (t >= 2): last use of Qs ----
    #pragma unroll
    for (int qi = 0; qi < 4; qi++) {
        int r = ty * 4 + qi;
        int i = I0 + r;
        int nstr = i >> 7;
        float qa = Qs[tx * QPAD + r];
        float qb = Qs[(tx + 32) * QPAD + r];
        for (int t = 2; t <= nstr; t++) {
            int j = i - (t << 7);
            float ka = q[(size_t)j * HD + tx];
            float kb = q[(size_t)j * HD + tx + 32];
            float p = qa * ka + qb * kb;
            p += __shfl_xor_sync(0xffffffffu, p, 16);
            p += __shfl_xor_sync(0xffffffffu, p, 8);
            p += __shfl_xor_sync(0xffffffffu, p, 4);
            p += __shfl_xor_sync(0xffffffffu, p, 2);
            p += __shfl_xor_sync(0xffffffffu, p, 1);
            if (tx == 0) Sstr[r * 16 + t] = p * 0.125f + am[j];
        }
    }
    __syncthreads();   // Qs dead everywhere -> Cstr may alias it

    // ---- softmax + strided ctx (writes Cstr over old Qs) ----
    #pragma unroll
    for (int qi = 0; qi < 4; qi++) {
        int r = ty * 4 + qi;
        int i = I0 + r;
        int nstr = i >> 7;

        float mx = -CUDART_INF_F;
        #pragma unroll
        for (int u = 0; u < 5; u++) mx = fmaxf(mx, Ps[(tx + 32 * u) * PPAD + r]);
        if (tx + 2 <= nstr) mx = fmaxf(mx, Sstr[r * 16 + tx + 2]);
        mx = fmaxf(mx, __shfl_xor_sync(0xffffffffu, mx, 16));
        mx = fmaxf(mx, __shfl_xor_sync(0xffffffffu, mx, 8));
        mx = fmaxf(mx, __shfl_xor_sync(0xffffffffu, mx, 4));
        mx = fmaxf(mx, __shfl_xor_sync(0xffffffffu, mx, 2));
        mx = fmaxf(mx, __shfl_xor_sync(0xffffffffu, mx, 1));

        float s = 0.0f;
        float e[5];
        #pragma unroll
        for (int u = 0; u < 5; u++) {
            e[u] = __expf(Ps[(tx + 32 * u) * PPAD + r] - mx);
            s += e[u];
        }
        float es = 0.0f;
        if (tx + 2 <= nstr) es = __expf(Sstr[r * 16 + tx + 2] - mx);
        s += es;
        s += __shfl_xor_sync(0xffffffffu, s, 16);
        s += __shfl_xor_sync(0xffffffffu, s, 8);
        s += __shfl_xor_sync(0xffffffffu, s, 4);
        s += __shfl_xor_sync(0xffffffffu, s, 2);
        s += __shfl_xor_sync(0xffffffffu, s, 1);
        float inv = 1.0f / s;

        #pragma unroll
        for (int u = 0; u < 5; u++) Ps[(tx + 32 * u) * PPAD + r] = e[u] * inv;

        float ax = 0.0f, ay = 0.0f;
        float pn = es * inv;
        for (int t = 2; t <= nstr; t++) {
            float p = __shfl_sync(0xffffffffu, pn, t - 2);
            int j = i - (t << 7);
            ax = fmaf(p, v[(size_t)j * HD + tx], ax);
            ay = fmaf(p, v[(size_t)j * HD + tx + 32], ay);
        }
        Cstr[r * CPAD + tx]      = ax;
        Cstr[r * CPAD + tx + 32] = ay;
    }
    __syncthreads();   // V staged + Cstr written before dense ctx

    // ---- dense ctx GEMM: 4 queries x 2 d-cols per thread (float2 loads) ----
    float o[4][2];
    #pragma unroll
    for (int qi = 0; qi < 4; qi++) { o[qi][0] = 0.0f; o[qi][1] = 0.0f; }

    #pragma unroll 4
    for (int c = 0; c < WIN; c++) {
        float2 bv2 = ((const float2*)(KV + c * HD))[tx];
        #pragma unroll
        for (int qi = 0; qi < 4; qi++) {
            float a = Ps[c * PPAD + ty * 4 + qi];
            o[qi][0] = fmaf(a, bv2.x, o[qi][0]);
            o[qi][1] = fmaf(a, bv2.y, o[qi][1]);
        }
    }

    // ---- epilogue: add strided ctx, store [B, S, H*64] ----
    #pragma unroll
    for (int qi = 0; qi < 4; qi++) {
        int r = ty * 4 + qi;
        int i = I0 + r;
        float2 cs = ((const float2*)(Cstr + r * CPAD))[tx];
        float2 res;
        res.x = o[qi][0] + cs.x;
        res.y = o[qi][1] + cs.y;
        *(float2*)(out + ((size_t)(b * S2 + i) * (NH * HD)) + (bh & 15) * HD + 2 * tx) = res;
    }
}

// ---------------------------------------------------------------------------
// Launch
// Inputs (metadata order): hidden_states, attention_mask, W_q, b_q, W_v, b_v
// ---------------------------------------------------------------------------
extern "C" void kernel_launch(void* const* d_in, const int* in_sizes, int n_in,
                              void* d_out, int out_size)
{
    const float* hidden = (const float*)d_in[0];
    const float* amask  = (const float*)d_in[1];
    const float* Wq     = (const float*)d_in[2];
    const float* bq     = (const float*)d_in[3];
    const float* Wv     = (const float*)d_in[4];
    const float* bv     = (const float*)d_in[5];
    float* out = (float*)d_out;

    cudaFuncSetAttribute(attn_kernel,
                         cudaFuncAttributeMaxDynamicSharedMemorySize,
                         ATTN_SMEM_BYTES);

    dim3 pgrid(HID / 128, (BATCH * S2) / 128, 2);   // (8, 32, 2)
    proj_kernel<<<pgrid, 256>>>(hidden, Wq, bq, Wv, bv);

    dim3 agrid(S2 / TQ, BATCH * NH);                // (64, 32)
    attn_kernel<<<agrid, 256, ATTN_SMEM_BYTES>>>(amask, out);
}

// round 8
// speedup vs baseline: 1.5286x; 1.0183x over previous
#include <cuda_runtime.h>
#include <cuda_fp16.h>
#include <math_constants.h>
#include <cstdint>

// Problem constants
#define S2    2048
#define HID   1024
#define NH    16
#define HD    64
#define BATCH 2

// Scratch for projected Q and V in [B, H, S, d] layout (16 MB each).
__device__ float g_q[BATCH * NH * S2 * HD];
__device__ float g_v[BATCH * NH * S2 * HD];

// ---------------------------------------------------------------------------
// FP16 tensor-core projection GEMM (measured ~47us for both projections).
// Block 128x128, k-block 32, double-buffered smem, ldmatrix operand loads.
// 8 warps, each 64(m) x 32(n) via mma.sync m16n8k16 (4 m-frags x 4 n-frags).
// ---------------------------------------------------------------------------
#define PKB 32
#define AKP 40    // A smem k-pad (halves)
#define BNP 136   // B smem n-pad (halves)

__device__ __forceinline__ uint2 f4_to_h4(float4 v) {
    __half2 h0 = __floats2half2_rn(v.x, v.y);
    __half2 h1 = __floats2half2_rn(v.z, v.w);
    uint2 r;
    r.x = *(uint32_t*)&h0;
    r.y = *(uint32_t*)&h1;
    return r;
}

__device__ __forceinline__ void ldsm_x4(uint32_t& r0, uint32_t& r1,
                                        uint32_t& r2, uint32_t& r3,
                                        const __half* p) {
    uint32_t a = (uint32_t)__cvta_generic_to_shared(p);
    asm volatile("ldmatrix.sync.aligned.m8n8.x4.shared.b16 {%0,%1,%2,%3}, [%4];"
                 : "=r"(r0), "=r"(r1), "=r"(r2), "=r"(r3) : "r"(a));
}

__device__ __forceinline__ void ldsm_x2_trans(uint32_t& r0, uint32_t& r1,
                                              const __half* p) {
    uint32_t a = (uint32_t)__cvta_generic_to_shared(p);
    asm volatile("ldmatrix.sync.aligned.m8n8.x2.trans.shared.b16 {%0,%1}, [%2];"
                 : "=r"(r0), "=r"(r1) : "r"(a));
}

__device__ __forceinline__ void mma_f16(float c[4], const uint32_t a[4],
                                        const uint32_t b[2]) {
    asm volatile(
        "mma.sync.aligned.m16n8k16.row.col.f32.f16.f16.f32 "
        "{%0,%1,%2,%3}, {%4,%5,%6,%7}, {%8,%9}, {%0,%1,%2,%3};"
        : "+f"(c[0]), "+f"(c[1]), "+f"(c[2]), "+f"(c[3])
        : "r"(a[0]), "r"(a[1]), "r"(a[2]), "r"(a[3]), "r"(b[0]), "r"(b[1]));
}

__global__ __launch_bounds__(256)
void proj_kernel(const float* __restrict__ A,
                 const float* __restrict__ Wq, const float* __restrict__ bq,
                 const float* __restrict__ Wv, const float* __restrict__ bv)
{
    const float* __restrict__ W    = blockIdx.z ? Wv : Wq;
    const float* __restrict__ bias = blockIdx.z ? bv : bq;
    float* __restrict__ out        = blockIdx.z ? g_v : g_q;

    __shared__ __half As[2][128][AKP];   // [m][k] row-major halves
    __shared__ __half Bs[2][PKB][BNP];   // [k][n] row-major halves

    const int tid  = threadIdx.x;
    const int lane = tid & 31;
    const int wid  = tid >> 5;
    const int gid  = lane >> 2;
    const int tig  = lane & 3;
    const int m0   = blockIdx.y * 128;
    const int n0   = blockIdx.x * 128;

    const int mBase = (wid >> 2) * 64;
    const int nBase = (wid & 3) * 32;

    const int a_row = (lane & 7) + 8 * ((lane >> 3) & 1);
    const int a_col = 8 * (lane >> 4);
    const int b_row = lane & 15;

    float c[4][4][4];
    #pragma unroll
    for (int f = 0; f < 4; f++)
        #pragma unroll
        for (int g = 0; g < 4; g++)
            #pragma unroll
            for (int i = 0; i < 4; i++) c[f][g][i] = 0.0f;

    uint2 pa[4], pb[4];

    #pragma unroll
    for (int p = 0; p < 4; p++) {
        int s = tid + 256 * p;
        int m = s >> 3, kq = s & 7;
        pa[p] = f4_to_h4(*(const float4*)(A + (size_t)(m0 + m) * HID + 4 * kq));
        int kr = s >> 5, nq = s & 31;
        pb[p] = f4_to_h4(*(const float4*)(W + (size_t)kr * HID + n0 + 4 * nq));
    }
    #pragma unroll
    for (int p = 0; p < 4; p++) {
        int s = tid + 256 * p;
        int m = s >> 3, kq = s & 7;
        *(uint2*)&As[0][m][4 * kq] = pa[p];
        int kr = s >> 5, nq = s & 31;
        *(uint2*)&Bs[0][kr][4 * nq] = pb[p];
    }
    __syncthreads();

    const int NKB = HID / PKB;   // 32
    for (int kb = 0; kb < NKB; kb++) {
        const int cur = kb & 1;
        const int nxt = cur ^ 1;

        if (kb + 1 < NKB) {
            const int kk = (kb + 1) * PKB;
            #pragma unroll
            for (int p = 0; p < 4; p++) {
                int s = tid + 256 * p;
                int m = s >> 3, kq = s & 7;
                pa[p] = f4_to_h4(*(const float4*)(A + (size_t)(m0 + m) * HID + kk + 4 * kq));
                int kr = s >> 5, nq = s & 31;
                pb[p] = f4_to_h4(*(const float4*)(W + (size_t)(kk + kr) * HID + n0 + 4 * nq));
            }
        }

        #pragma unroll
        for (int ks = 0; ks < PKB; ks += 16) {
            uint32_t a[4][4], b[4][2];
            #pragma unroll
            for (int f = 0; f < 4; f++)
                ldsm_x4(a[f][0], a[f][1], a[f][2], a[f][3],
                        &As[cur][mBase + 16 * f + a_row][ks + a_col]);
            #pragma unroll
            for (int g = 0; g < 4; g++)
                ldsm_x2_trans(b[g][0], b[g][1],
                              &Bs[cur][ks + b_row][nBase + 8 * g]);
            #pragma unroll
            for (int f = 0; f < 4; f++)
                #pragma unroll
                for (int g = 0; g < 4; g++)
                    mma_f16(c[f][g], a[f], b[g]);
        }

        if (kb + 1 < NKB) {
            #pragma unroll
            for (int p = 0; p < 4; p++) {
                int s = tid + 256 * p;
                int m = s >> 3, kq = s & 7;
                *(uint2*)&As[nxt][m][4 * kq] = pa[p];
                int kr = s >> 5, nq = s & 31;
                *(uint2*)&Bs[nxt][kr][4 * nq] = pb[p];
            }
        }
        __syncthreads();
    }

    #pragma unroll
    for (int g = 0; g < 4; g++) {
        const int n  = n0 + nBase + 8 * g + 2 * tig;
        const int h  = n >> 6;
        const int cc = n & 63;
        const float b0 = bias[n];
        const float b1 = bias[n + 1];
        #pragma unroll
        for (int f = 0; f < 4; f++) {
            #pragma unroll
            for (int half = 0; half < 2; half++) {
                int m  = m0 + mBase + 16 * f + gid + 8 * half;
                int bb = m >> 11;
                int s  = m & 2047;
                float2 o;
                o.x = c[f][g][2 * half + 0] + b0;
                o.y = c[f][g][2 * half + 1] + b1;
                *(float2*)(out + (((size_t)(bb * NH + h) * S2 + s) * HD + cc)) = o;
            }
        }
    }
}

// ---------------------------------------------------------------------------
// Tiled sparse attention — wavefront-optimized.
// KV: Kt [d][161] (score phase) / V [c][64] row-major (ctx phase, aliased)
// Qs: [d][36] transposed, 16B-aligned rows -> float4 BROADCAST in score GEMM.
//     Aliased by Cstr [r][66] after Qs is dead (full barrier between).
// Ps: [r][168] row-major -> score stores stride-1, softmax stride-1, ctx
//     reads as float4 BROADCAST per 4-key group.
// smem: 64*161 + 64*36 + 32*168 + 32*16 = 18496 floats = 73,984 B -> 3 CTAs/SM.
// Masked entries are exactly 0 after softmax (fp32 exp underflow) -> exact.
// ---------------------------------------------------------------------------
#define TQ    32
#define WIN   160
#define KPAD  161
#define QPAD  36
#define PSW   168
#define CPAD  66

#define ATTN_SMEM_FLOATS (64*KPAD + 64*QPAD + TQ*PSW + TQ*16)
#define ATTN_SMEM_BYTES  (ATTN_SMEM_FLOATS * 4)

__global__ __launch_bounds__(256, 3)
void attn_kernel(const float* __restrict__ amask, float* __restrict__ out)
{
    extern __shared__ float sm[];
    float* KV   = sm;                        // 64*161
    float* QC   = KV + 64 * KPAD;            // Qs [64][36] then Cstr [32][66]
    float* Ps   = QC + 64 * QPAD;            // [32][168]
    float* Sstr = Ps + TQ * PSW;             // [32][16]
    float* Qs   = QC;
    float* Cstr = QC;

    const int tid = threadIdx.x;
    const int tx  = tid & 31;
    const int ty  = tid >> 5;
    const int I0  = blockIdx.x * TQ;
    const int bh  = blockIdx.y;
    const int b   = bh >> 4;
    const int jbase = I0 - 128;

    const float* __restrict__ q  = g_q + (size_t)bh * S2 * HD;
    const float* __restrict__ v  = g_v + (size_t)bh * S2 * HD;
    const float* __restrict__ am = amask + b * S2;

    // ---- stage Q tile (transposed [d][36]) and K window (transposed) ----
    for (int idx = tid; idx < TQ * HD; idx += 256) {
        int r = idx >> 6, d = idx & 63;
        Qs[d * QPAD + r] = q[(size_t)(I0 + r) * HD + d];
    }
    for (int idx = tid; idx < WIN * HD; idx += 256) {
        int c = idx >> 6, d = idx & 63;
        int j = jbase + c;
        KV[d * KPAD + c] = (j >= 0) ? q[(size_t)j * HD + d] : 0.0f;
    }
    __syncthreads();

    // ---- dense score GEMM: 4 queries x 5 keys per thread ----
    // Qs row is 16B-aligned -> one float4 broadcast per d (was 4 scalars).
    float acc[4][5];
    #pragma unroll
    for (int qi = 0; qi < 4; qi++)
        #pragma unroll
        for (int u = 0; u < 5; u++) acc[qi][u] = 0.0f;

    #pragma unroll 8
    for (int d = 0; d < 64; d++) {
        float4 a4 = *(const float4*)&Qs[d * QPAD + 4 * ty];
        #pragma unroll
        for (int u = 0; u < 5; u++) {
            float bb = KV[d * KPAD + tx + 32 * u];
            acc[0][u] = fmaf(a4.x, bb, acc[0][u]);
            acc[1][u] = fmaf(a4.y, bb, acc[1][u]);
            acc[2][u] = fmaf(a4.z, bb, acc[2][u]);
            acc[3][u] = fmaf(a4.w, bb, acc[3][u]);
        }
    }

    // mask + scale + attention_mask -> Ps row-major [r][c]
    #pragma unroll
    for (int u = 0; u < 5; u++) {
        int c = tx + 32 * u;
        int j = jbase + c;
        float amv = (j >= 0) ? am[j] : 0.0f;
        #pragma unroll
        for (int qi = 0; qi < 4; qi++) {
            int r = ty * 4 + qi;
            bool ok = (c >= r) && (c <= r + 128) && (j >= 0);
            Ps[r * PSW + c] = ok ? (acc[qi][u] * 0.125f + amv) : -CUDART_INF_F;
        }
    }
    __syncthreads();   // K reads done -> safe to overwrite KV with V

    // ---- stage V window row-major [c][64] (float4) ----
    for (int idx = tid; idx < WIN * 16; idx += 256) {
        int c = idx >> 4, dq = idx & 15;
        int j = jbase + c;
        float4 val = (j >= 0) ? *(const float4*)(v + (size_t)j * HD + 4 * dq)
                              : make_float4(0.f, 0.f, 0.f, 0.f);
        *(float4*)(KV + c * HD + 4 * dq) = val;
    }

    // ---- strided scores (t >= 2): last use of Qs ----
    #pragma unroll
    for (int qi = 0; qi < 4; qi++) {
        int r = ty * 4 + qi;
        int i = I0 + r;
        int nstr = i >> 7;
        float qa = Qs[tx * QPAD + r];
        float qb = Qs[(tx + 32) * QPAD + r];
        for (int t = 2; t <= nstr; t++) {
            int j = i - (t << 7);
            float ka = q[(size_t)j * HD + tx];
            float kb = q[(size_t)j * HD + tx + 32];
            float p = qa * ka + qb * kb;
            p += __shfl_xor_sync(0xffffffffu, p, 16);
            p += __shfl_xor_sync(0xffffffffu, p, 8);
            p += __shfl_xor_sync(0xffffffffu, p, 4);
            p += __shfl_xor_sync(0xffffffffu, p, 2);
            p += __shfl_xor_sync(0xffffffffu, p, 1);
            if (tx == 0) Sstr[r * 16 + t] = p * 0.125f + am[j];
        }
    }
    __syncthreads();   // Qs dead everywhere -> Cstr may alias it

    // ---- softmax + strided ctx (writes Cstr over old Qs) ----
    #pragma unroll
    for (int qi = 0; qi < 4; qi++) {
        int r = ty * 4 + qi;
        int i = I0 + r;
        int nstr = i >> 7;

        float mx = -CUDART_INF_F;
        #pragma unroll
        for (int u = 0; u < 5; u++) mx = fmaxf(mx, Ps[r * PSW + tx + 32 * u]);
        if (tx + 2 <= nstr) mx = fmaxf(mx, Sstr[r * 16 + tx + 2]);
        mx = fmaxf(mx, __shfl_xor_sync(0xffffffffu, mx, 16));
        mx = fmaxf(mx, __shfl_xor_sync(0xffffffffu, mx, 8));
        mx = fmaxf(mx, __shfl_xor_sync(0xffffffffu, mx, 4));
        mx = fmaxf(mx, __shfl_xor_sync(0xffffffffu, mx, 2));
        mx = fmaxf(mx, __shfl_xor_sync(0xffffffffu, mx, 1));

        float s = 0.0f;
        float e[5];
        #pragma unroll
        for (int u = 0; u < 5; u++) {
            e[u] = __expf(Ps[r * PSW + tx + 32 * u] - mx);
            s += e[u];
        }
        float es = 0.0f;
        if (tx + 2 <= nstr) es = __expf(Sstr[r * 16 + tx + 2] - mx);
        s += es;
        s += __shfl_xor_sync(0xffffffffu, s, 16);
        s += __shfl_xor_sync(0xffffffffu, s, 8);
        s += __shfl_xor_sync(0xffffffffu, s, 4);
        s += __shfl_xor_sync(0xffffffffu, s, 2);
        s += __shfl_xor_sync(0xffffffffu, s, 1);
        float inv = 1.0f / s;

        #pragma unroll
        for (int u = 0; u < 5; u++) Ps[r * PSW + tx + 32 * u] = e[u] * inv;

        float ax = 0.0f, ay = 0.0f;
        float pn = es * inv;
        for (int t = 2; t <= nstr; t++) {
            float p = __shfl_sync(0xffffffffu, pn, t - 2);
            int j = i - (t << 7);
            ax = fmaf(p, v[(size_t)j * HD + tx], ax);
            ay = fmaf(p, v[(size_t)j * HD + tx + 32], ay);
        }
        Cstr[r * CPAD + tx]      = ax;
        Cstr[r * CPAD + tx + 32] = ay;
    }
    __syncthreads();   // V staged + Ps normalized + Cstr written

    // ---- dense ctx GEMM: 4 queries x 2 d-cols per thread, keys in groups
    //      of 4 so P comes in as one float4 broadcast per query row. ----
    float o[4][2];
    #pragma unroll
    for (int qi = 0; qi < 4; qi++) { o[qi][0] = 0.0f; o[qi][1] = 0.0f; }

    #pragma unroll 2
    for (int c4 = 0; c4 < WIN / 4; c4++) {
        float2 v0 = *(const float2*)(KV + (4 * c4 + 0) * HD + 2 * tx);
        float2 v1 = *(const float2*)(KV + (4 * c4 + 1) * HD + 2 * tx);
        float2 v2 = *(const float2*)(KV + (4 * c4 + 2) * HD + 2 * tx);
        float2 v3 = *(const float2*)(KV + (4 * c4 + 3) * HD + 2 * tx);
        #pragma unroll
        for (int qi = 0; qi < 4; qi++) {
            float4 pp = *(const float4*)&Ps[(4 * ty + qi) * PSW + 4 * c4];
            o[qi][0] = fmaf(pp.x, v0.x, o[qi][0]);
            o[qi][0] = fmaf(pp.y, v1.x, o[qi][0]);
            o[qi][0] = fmaf(pp.z, v2.x, o[qi][0]);
            o[qi][0] = fmaf(pp.w, v3.x, o[qi][0]);
            o[qi][1] = fmaf(pp.x, v0.y, o[qi][1]);
            o[qi][1] = fmaf(pp.y, v1.y, o[qi][1]);
            o[qi][1] = fmaf(pp.z, v2.y, o[qi][1]);
            o[qi][1] = fmaf(pp.w, v3.y, o[qi][1]);
        }
    }

    // ---- epilogue: add strided ctx, store [B, S, H*64] ----
    #pragma unroll
    for (int qi = 0; qi < 4; qi++) {
        int r = ty * 4 + qi;
        int i = I0 + r;
        float2 cs = ((const float2*)(Cstr + r * CPAD))[tx];
        float2 res;
        res.x = o[qi][0] + cs.x;
        res.y = o[qi][1] + cs.y;
        *(float2*)(out + ((size_t)(b * S2 + i) * (NH * HD)) + (bh & 15) * HD + 2 * tx) = res;
    }
}

// ---------------------------------------------------------------------------
// Launch
// Inputs (metadata order): hidden_states, attention_mask, W_q, b_q, W_v, b_v
// ---------------------------------------------------------------------------
extern "C" void kernel_launch(void* const* d_in, const int* in_sizes, int n_in,
                              void* d_out, int out_size)
{
    const float* hidden = (const float*)d_in[0];
    const float* amask  = (const float*)d_in[1];
    const float* Wq     = (const float*)d_in[2];
    const float* bq     = (const float*)d_in[3];
    const float* Wv     = (const float*)d_in[4];
    const float* bv     = (const float*)d_in[5];
    float* out = (float*)d_out;

    cudaFuncSetAttribute(attn_kernel,
                         cudaFuncAttributeMaxDynamicSharedMemorySize,
                         ATTN_SMEM_BYTES);

    dim3 pgrid(HID / 128, (BATCH * S2) / 128, 2);   // (8, 32, 2)
    proj_kernel<<<pgrid, 256>>>(hidden, Wq, bq, Wv, bv);

    dim3 agrid(S2 / TQ, BATCH * NH);                // (64, 32)
    attn_kernel<<<agrid, 256, ATTN_SMEM_BYTES>>>(amask, out);
}